// round 14
// baseline (speedup 1.0000x reference)
#include <cuda_runtime.h>
#include <cuda_fp16.h>
#include <cstdint>

// Problem constants (fixed by the dataset)
#define N_PTS   300000
#define INC     128
#define BATCH   4
#define GXD     50
#define GYD     50
#define GZD     4
#define NCELLS  40000          // BATCH*GXD*GYD*GZD
#define NFCH    256            // 2*INC feature channels (cos | sin)

// Scratch (static device globals — no allocation allowed)
__device__ float    g_grid[NCELLS * NFCH];  // scatter target [cell][256]
__device__ float    g_cnt [NCELLS];         // per-cell point count
__device__ float    g_tmp [NCELLS * NFCH];  // y/z box-summed features
__device__ float    g_tmpc[NCELLS];         // y/z box-summed counts
__device__ float    g_agg [NCELLS * NFCH];  // final per-cell averages
__device__ uint32_t g_WHi[128 * 64];        // W fp16-split hi (packed half2 words)
__device__ uint32_t g_WLo[128 * 64];        // W fp16-split lo

__device__ __forceinline__ int vid_of(int4 cd) {
    return ((cd.w * GXD + (cd.x >> 3)) * GYD + (cd.y >> 3)) * GZD + (cd.z >> 3);
}

// sin/cos: explicit range reduction into [-pi, pi], then HW MUFU intrinsics.
__device__ __forceinline__ void sincos_red(float x, float* s, float* c) {
    float r = x - 6.283185307179586f * rintf(x * 0.15915494309189535f);
    *s = __sinf(r);
    *c = __cosf(r);
}

// Vectorized float4 reduction (PTX ISA 8.1, sm_90+ base feature)
__device__ __forceinline__ void red_add_v4(float* p, float4 v) {
    asm volatile("red.global.add.v4.f32 [%0], {%1, %2, %3, %4};"
                 :: "l"(p), "f"(v.x), "f"(v.y), "f"(v.z), "f"(v.w) : "memory");
}

// split (v0,v1) into packed half2 hi + half2 lo
__device__ __forceinline__ void cvt_split(float v0, float v1,
                                          uint32_t& hi, uint32_t& lo) {
    __half h0 = __float2half_rn(v0);
    __half h1 = __float2half_rn(v1);
    __half l0 = __float2half_rn(v0 - __half2float(h0));
    __half l1 = __float2half_rn(v1 - __half2float(h1));
    hi = ((uint32_t)__half_as_ushort(h1) << 16) | __half_as_ushort(h0);
    lo = ((uint32_t)__half_as_ushort(l1) << 16) | __half_as_ushort(l0);
}

__device__ __forceinline__ uint32_t smem_u32(const void* p) {
    return (uint32_t)__cvta_generic_to_shared(p);
}

// ldmatrix x4 (sm_75+): four 8x8 b16 matrices, lane-address groups of 8.
__device__ __forceinline__ void ldsm_x4(uint32_t* r, uint32_t addr) {
    asm volatile("ldmatrix.sync.aligned.m8n8.x4.shared.b16 {%0,%1,%2,%3}, [%4];"
                 : "=r"(r[0]), "=r"(r[1]), "=r"(r[2]), "=r"(r[3]) : "r"(addr));
}

// ---------------------------------------------------------------------------
// KW: one-shot fp16 split of W (128x128) into packed word arrays
// ---------------------------------------------------------------------------
__global__ void k_wsplit(const float* __restrict__ Wm) {
    int i = blockIdx.x * blockDim.x + threadIdx.x;   // word index 0..8191
    if (i >= 128 * 64) return;
    int row = i >> 6, c2 = i & 63;
    const float2 v = *reinterpret_cast<const float2*>(Wm + (size_t)row * 128 + 2 * c2);
    uint32_t hi, lo;
    cvt_split(v.x, v.y, hi, lo);
    g_WHi[i] = hi;
    g_WLo[i] = lo;
}

// ---------------------------------------------------------------------------
// K0a/K0b: zero the scatter grid + counts (split so GEMM is 4th launch)
// ---------------------------------------------------------------------------
#define HALF_GRID4 ((NCELLS * NFCH) / 8)     // float4 count of half the grid
__global__ void k_zero_a() {
    int i = blockIdx.x * blockDim.x + threadIdx.x;
    if (i < HALF_GRID4)
        reinterpret_cast<float4*>(g_grid)[i] = make_float4(0.f, 0.f, 0.f, 0.f);
}
__global__ void k_zero_b() {
    int i = blockIdx.x * blockDim.x + threadIdx.x;
    float4 z = make_float4(0.f, 0.f, 0.f, 0.f);
    if (i < HALF_GRID4) reinterpret_cast<float4*>(g_grid)[HALF_GRID4 + i] = z;
    if (i < NCELLS / 4) reinterpret_cast<float4*>(g_cnt)[i] = z;
}

// ---------------------------------------------------------------------------
// K1: PERSISTENT fused fp16x3-split mma.sync GEMM (ldmatrix loads) +
//     LayerNorm + sincos + WARP-LOCAL staged red.v4 scatter.
//     296 CTAs (2/SM), 256 threads, warp tile 32x32 (wr=w>>2, nc=w&3).
//     Epilogue is fully warp-local: warp (wr,nc) owns channel quarter
//     [nc*32, nc*32+32) (cos+sin) of its 32 rows; it stages 16 rows at a
//     time in a private 4KB buffer and scatters with per-lane red.v4.
//     NO block barriers in the epilogue (only __syncwarp).
// ---------------------------------------------------------------------------
#define LDA   136                       // halves per smem row (8-half pad)
#define A_TILE_BYTES (64  * LDA * 2)    // 17408
#define B_TILE_BYTES (128 * LDA * 2)    // 34816

#define OFF_B_HI  0
#define OFF_B_LO  (OFF_B_HI + B_TILE_BYTES)      // 34816
#define OFF_R     (OFF_B_LO + B_TILE_BYTES)      // 69632: region R (34816 B)
#define OFF_A_HI  OFF_R
#define OFF_A_LO  (OFF_A_HI + A_TILE_BYTES)      // 87040
#define OFF_HS    OFF_R                          // 8 warps x 4KB = 32768 B
#define OFF_COORD (OFF_R + A_TILE_BYTES * 2)     // 104448: int4[64] = 1024
#define OFF_VID   (OFF_COORD + 1024)             // 105472: int[64] = 256
#define OFF_GB    (OFF_VID + 256)                // 105728: float2[128] = 1024
#define OFF_WP4   (OFF_GB + 1024)                // 106752: float4[128] = 2048
#define OFF_PS    (OFF_WP4 + 2048)               // 108800: 2 x [64][4] = 2048
#define SMEM_BYTES (OFF_PS + 2048)               // 110848 -> 2 CTAs/SM

#define GRID_PERSIST 296

__device__ __forceinline__ void mma16816(float* c,
                                         uint32_t a0, uint32_t a1,
                                         uint32_t a2, uint32_t a3,
                                         uint32_t b0, uint32_t b1) {
    asm volatile(
        "mma.sync.aligned.m16n8k16.row.col.f32.f16.f16.f32 "
        "{%0,%1,%2,%3}, {%4,%5,%6,%7}, {%8,%9}, {%0,%1,%2,%3};"
        : "+f"(c[0]), "+f"(c[1]), "+f"(c[2]), "+f"(c[3])
        : "r"(a0), "r"(a1), "r"(a2), "r"(a3), "r"(b0), "r"(b1));
}

__global__ void __launch_bounds__(256, 2)
k_gemm_ln_scatter(const float* __restrict__ x,
                  const int*   __restrict__ coords,
                  const float* __restrict__ gamma,
                  const float* __restrict__ beta,
                  const float* __restrict__ Wp)
{
    extern __shared__ char smraw[];
    __half* BsHi = (__half*)(smraw + OFF_B_HI);
    __half* BsLo = (__half*)(smraw + OFF_B_LO);
    __half* AsHi = (__half*)(smraw + OFF_A_HI);
    __half* AsLo = (__half*)(smraw + OFF_A_LO);
    int4*   sCd  = (int4*)  (smraw + OFF_COORD);
    int*    sVid = (int*)   (smraw + OFF_VID);
    float2* sGB  = (float2*)(smraw + OFF_GB);
    float4* sWp4 = (float4*)(smraw + OFF_WP4);
    float*  sPS  = (float*) (smraw + OFF_PS);        // [64][4] partial sums
    float*  sPQ  = (float*) (smraw + OFF_PS + 1024); // [64][4] partial sqsums

    const int tid = threadIdx.x;

    // ---- One-time: stage W (uint2 = 8 halves per iter) + packed params ----
    {
        const uint2* whi = (const uint2*)g_WHi;
        const uint2* wlo = (const uint2*)g_WLo;
        #pragma unroll
        for (int it = 0; it < 16; it++) {
            int i2  = it * 256 + tid;          // 0..4095
            int row = i2 >> 5, c4 = i2 & 31;   // 32 uint2 per row (128 halves)
            uint2 h = whi[i2], l = wlo[i2];
            *(uint2*)(BsHi + row * LDA + 4 * c4) = h;
            *(uint2*)(BsLo + row * LDA + 4 * c4) = l;
        }
        if (tid < 128) {
            sGB[tid]  = make_float2(gamma[tid], beta[tid]);
            sWp4[tid] = make_float4(Wp[tid], Wp[128 + tid], Wp[256 + tid], 0.f);
        }
    }

    const int w    = tid >> 5;       // 0..7
    const int lane = tid & 31;
    const int g    = lane >> 2;      // groupID
    const int t    = lane & 3;       // thread-in-group
    const int wr   = w >> 2;         // row group 0..1 (32 rows each)
    const int nc   = w & 3;          // col group 0..3 (32 cols each)
    const int w32  = wr * 32;
    const int nt0  = nc * 4;         // first n-tile (8-col tiles)

    // Per-warp private staging buffer: 16 rows x 16 float4 groups = 4 KB
    float*  HsW  = (float*) (smraw + OFF_HS + w * 4096);
    float4* HsW4 = (float4*)(smraw + OFF_HS + w * 4096);

    // ---- ldmatrix per-lane byte offsets (within a tile, k16 = 0) ----
    const int lq = lane & 7;
    uint32_t aoff[2];
    #pragma unroll
    for (int m = 0; m < 2; m++) {
        int row = w32 + m * 16 + lq + ((lane >> 3) & 1) * 8;
        int col = ((lane >> 4) & 1) * 8;
        aoff[m] = (uint32_t)((row * LDA + col) * 2);
    }
    uint32_t boff[2];
    #pragma unroll
    for (int p = 0; p < 2; p++) {
        int row = (nt0 + 2 * p + (lane >> 4)) * 8 + lq;
        int col = ((lane >> 3) & 1) * 8;
        boff[p] = (uint32_t)((row * LDA + col) * 2);
    }
    const uint32_t aHiB = smem_u32(AsHi), aLoB = smem_u32(AsLo);
    const uint32_t bHiB = smem_u32(BsHi), bLoB = smem_u32(BsLo);

    const int n_tiles = (N_PTS + 63) / 64;

    for (int tile = blockIdx.x; tile < n_tiles; tile += GRID_PERSIST) {
        const int row0 = tile * 64;
        __syncthreads();   // previous tile's warp-local scatter reads are done

        // ---- Stage x tile into A (inside region R): 4 threads per row ----
        {
            int row = tid >> 2, sel = tid & 3;     // row 0..63
            int gr = row0 + row;
            if (gr < N_PTS) {
                const float4* xrow = (const float4*)(x + (size_t)gr * 128) + sel * 8;
                #pragma unroll
                for (int q = 0; q < 8; q++) {
                    float4 v = xrow[q];
                    int c = sel * 32 + q * 4;
                    uint32_t hi, lo;
                    cvt_split(v.x, v.y, hi, lo);
                    *(uint32_t*)(AsHi + row * LDA + c)     = hi;
                    *(uint32_t*)(AsLo + row * LDA + c)     = lo;
                    cvt_split(v.z, v.w, hi, lo);
                    *(uint32_t*)(AsHi + row * LDA + c + 2) = hi;
                    *(uint32_t*)(AsLo + row * LDA + c + 2) = lo;
                }
            } else {
                #pragma unroll
                for (int q = 0; q < 8; q++) {
                    int c = sel * 32 + q * 4;
                    *(uint32_t*)(AsHi + row * LDA + c)     = 0u;
                    *(uint32_t*)(AsLo + row * LDA + c)     = 0u;
                    *(uint32_t*)(AsHi + row * LDA + c + 2) = 0u;
                    *(uint32_t*)(AsLo + row * LDA + c + 2) = 0u;
                }
            }
        }
        if (tid < 64) {
            int gr = row0 + tid;
            int4 cd = (gr < N_PTS) ? *reinterpret_cast<const int4*>(&coords[(size_t)gr * 4])
                                   : make_int4(0, 0, 0, 0);
            sCd[tid]  = cd;
            sVid[tid] = vid_of(cd);
        }
        __syncthreads();

        // ---- Warp-tiled fused mainloop (ldmatrix operand loads) ----
        float acc[2][4][4];              // [m-group][n-tile][frag]
        #pragma unroll
        for (int m = 0; m < 2; m++)
            #pragma unroll
            for (int nt = 0; nt < 4; nt++)
                #pragma unroll
                for (int j = 0; j < 4; j++) acc[m][nt][j] = 0.f;

        #pragma unroll 2
        for (int k16 = 0; k16 < 8; k16++) {
            const uint32_t kb = (uint32_t)(k16 * 32);   // 16 halves = 32 bytes
            uint32_t ah[2][4], al[2][4], bh[2][4], bl[2][4];
            #pragma unroll
            for (int m = 0; m < 2; m++) {
                ldsm_x4(ah[m], aHiB + aoff[m] + kb);
                ldsm_x4(al[m], aLoB + aoff[m] + kb);
            }
            #pragma unroll
            for (int p = 0; p < 2; p++) {
                ldsm_x4(bh[p], bHiB + boff[p] + kb);
                ldsm_x4(bl[p], bLoB + boff[p] + kb);
            }
            #pragma unroll
            for (int p = 0; p < 2; p++) {
                #pragma unroll
                for (int j = 0; j < 2; j++) {
                    const int nt = 2 * p + j;
                    const uint32_t b0h = bh[p][2 * j], b1h = bh[p][2 * j + 1];
                    const uint32_t b0l = bl[p][2 * j], b1l = bl[p][2 * j + 1];
                    #pragma unroll
                    for (int m = 0; m < 2; m++) {
                        mma16816(acc[m][nt], ah[m][0], ah[m][1], ah[m][2], ah[m][3], b0h, b1h);
                        mma16816(acc[m][nt], al[m][0], al[m][1], al[m][2], al[m][3], b0h, b1h);
                        mma16816(acc[m][nt], ah[m][0], ah[m][1], ah[m][2], ah[m][3], b0l, b1l);
                    }
                }
            }
        }
        __syncthreads();   // done reading A; HsW may overwrite region R

        // ---- LayerNorm stats: 32-col partials, combine across col groups ----
        float ps[2][2], pq[2][2];
        #pragma unroll
        for (int m = 0; m < 2; m++) {
            float s0 = 0.f, q0 = 0.f, s1 = 0.f, q1 = 0.f;
            #pragma unroll
            for (int nt = 0; nt < 4; nt++) {
                s0 += acc[m][nt][0] + acc[m][nt][1];
                q0 += acc[m][nt][0] * acc[m][nt][0] + acc[m][nt][1] * acc[m][nt][1];
                s1 += acc[m][nt][2] + acc[m][nt][3];
                q1 += acc[m][nt][2] * acc[m][nt][2] + acc[m][nt][3] * acc[m][nt][3];
            }
            #pragma unroll
            for (int off = 1; off <= 2; off <<= 1) {
                s0 += __shfl_xor_sync(0xffffffffu, s0, off);
                q0 += __shfl_xor_sync(0xffffffffu, q0, off);
                s1 += __shfl_xor_sync(0xffffffffu, s1, off);
                q1 += __shfl_xor_sync(0xffffffffu, q1, off);
            }
            ps[m][0] = s0; pq[m][0] = q0;
            ps[m][1] = s1; pq[m][1] = q1;
        }
        if (t == 0) {
            #pragma unroll
            for (int m = 0; m < 2; m++) {
                int r0 = w32 + m * 16 + g;
                sPS[r0 * 4 + nc]       = ps[m][0];  sPQ[r0 * 4 + nc]       = pq[m][0];
                sPS[(r0 + 8) * 4 + nc] = ps[m][1];  sPQ[(r0 + 8) * 4 + nc] = pq[m][1];
            }
        }
        __syncthreads();

        float mu[2][2], rs[2][2];
        #pragma unroll
        for (int m = 0; m < 2; m++)
            #pragma unroll
            for (int i = 0; i < 2; i++) {
                int r = w32 + m * 16 + g + i * 8;
                float4 s4 = *(const float4*)(sPS + r * 4);
                float4 q4 = *(const float4*)(sPQ + r * 4);
                float s = s4.x + s4.y + s4.z + s4.w;
                float q = q4.x + q4.y + q4.z + q4.w;
                float m0 = s * (1.f / 128.f);
                float v0 = q * (1.f / 128.f) - m0 * m0;
                mu[m][i] = m0;
                rs[m][i] = rsqrtf(v0 + 1e-6f);
            }

        // Count channel: one atomic per point
        if (tid < 64 && row0 + tid < N_PTS)
            atomicAdd(&g_cnt[sVid[tid]], 1.0f);

        // ---- WARP-LOCAL epilogue + scatter: 2 chunks of 16 rows (chunk = m) --
        // Warp (wr,nc) owns channels [nc*32, nc*32+32) cos + same sin of its
        // 32 rows. Staging layout per chunk: HsW[row16][16 float4 groups],
        // groups 0..7 = cos quarter rotated by row16, 8..15 = sin quarter.
        #pragma unroll 1
        for (int c = 0; c < 2; c++) {
            // F-write 16 rows (m-group c): rows row16 = g + 8i
            #pragma unroll
            for (int i = 0; i < 2; i++) {
                int row16 = g + 8 * i;
                int r = w32 + c * 16 + row16;
                int4 cd = sCd[r];
                float fx = (float)cd.x, fy = (float)cd.y, fz = (float)cd.z;
                float muv = mu[c][i], rsv = rs[c][i];
                #pragma unroll
                for (int nt = 0; nt < 4; nt++) {
                    int c0 = (nt0 + nt) * 8 + 2 * t;
                    float2 gb0 = sGB[c0], gb1 = sGB[c0 + 1];
                    float4 wv0 = sWp4[c0], wv1 = sWp4[c0 + 1];
                    float h0 = (acc[c][nt][2 * i]     - muv) * rsv * gb0.x + gb0.y;
                    float h1 = (acc[c][nt][2 * i + 1] - muv) * rsv * gb1.x + gb1.y;
                    float sn0, cs0, sn1, cs1;
                    sincos_red(fx * wv0.x + fy * wv0.y + fz * wv0.z, &sn0, &cs0);
                    sincos_red(fx * wv1.x + fy * wv1.y + fz * wv1.z, &sn1, &cs1);
                    int lg  = nt * 2 + (t >> 1);            // local group 0..7
                    int pg  = (lg + row16) & 7;             // rotated
                    int e2  = (t & 1) * 2;                  // element pair
                    *(float2*)(HsW + row16 * 64 + pg * 4 + e2)        = make_float2(h0 * cs0, h1 * cs1);
                    *(float2*)(HsW + row16 * 64 + (8 + pg) * 4 + e2)  = make_float2(h0 * sn0, h1 * sn1);
                }
            }
            __syncwarp();

            // Scatter 16 points: lanes 0-15 row 2it, 16-31 row 2it+1;
            // gsel = lane&15 selects the float4 group.
            int gsel = lane & 15;
            #pragma unroll 1
            for (int it = 0; it < 8; it++) {
                int row16 = it * 2 + (lane >> 4);
                int r  = w32 + c * 16 + row16;
                int gp = row0 + r;
                if (gp < N_PTS) {
                    float4 v = HsW4[row16 * 16 + gsel];
                    int lg  = (gsel - row16) & 7;           // un-rotate
                    int off = (gsel < 8) ? (nt0 * 2 + lg) * 4
                                         : 128 + (nt0 * 2 + lg) * 4;
                    red_add_v4(g_grid + (size_t)sVid[r] * NFCH + off, v);
                }
            }
            __syncwarp();   // reads done before next chunk overwrites HsW
        }
    }
}

// ---------------------------------------------------------------------------
// K2a: 9-point box sum over (y,z), float4 channels. 4 cells per 256-thr block.
// ---------------------------------------------------------------------------
__global__ void k_box_yz() {
    int cell = blockIdx.x * 4 + (threadIdx.x >> 6);
    int ch4  = threadIdx.x & 63;
    int rem  = cell % (GYD * GZD);
    int cy   = rem / GZD;
    int cz   = rem % GZD;
    int dylo = (cy > 0) ? -1 : 0, dyhi = (cy < GYD - 1) ? 1 : 0;
    int dzlo = (cz > 0) ? -1 : 0, dzhi = (cz < GZD - 1) ? 1 : 0;

    const float4* grid4 = (const float4*)g_grid;
    float4 s = make_float4(0.f, 0.f, 0.f, 0.f);
    float  sc = 0.f;
    for (int dy = dylo; dy <= dyhi; dy++)
        for (int dz = dzlo; dz <= dzhi; dz++) {
            int nb = cell + dy * GZD + dz;
            float4 v = grid4[(size_t)nb * 64 + ch4];
            s.x += v.x; s.y += v.y; s.z += v.z; s.w += v.w;
            if (ch4 == 0) sc += g_cnt[nb];
        }
    ((float4*)g_tmp)[(size_t)cell * 64 + ch4] = s;
    if (ch4 == 0) g_tmpc[cell] = sc;
}

// ---------------------------------------------------------------------------
// K2b: 3-point sum over x + divide by count. 4 cells per 256-thread block.
// ---------------------------------------------------------------------------
__global__ void k_box_x_div() {
    int cell = blockIdx.x * 4 + (threadIdx.x >> 6);
    int ch4  = threadIdx.x & 63;
    int cx   = (cell % (GXD * GYD * GZD)) / (GYD * GZD);

    const float4* tmp4 = (const float4*)g_tmp;
    float4 num = make_float4(0.f, 0.f, 0.f, 0.f);
    float  den = 0.f;
    #pragma unroll
    for (int dx = -1; dx <= 1; dx++) {
        int xx = cx + dx;
        if (xx < 0 || xx >= GXD) continue;
        int nb = cell + dx * GYD * GZD;
        float4 v = tmp4[(size_t)nb * 64 + ch4];
        num.x += v.x; num.y += v.y; num.z += v.z; num.w += v.w;
        den += g_tmpc[nb];
    }
    float inv = 1.0f / fmaxf(den, 1e-12f);
    float4 r = make_float4(num.x * inv, num.y * inv, num.z * inv, num.w * inv);
    ((float4*)g_agg)[(size_t)cell * 64 + ch4] = r;
}

// ---------------------------------------------------------------------------
// K3: gather + recombine, float4: warp per point, lane = float4 group (c4g)
// ---------------------------------------------------------------------------
__global__ void k_gather(const int* __restrict__ coords,
                         const float* __restrict__ Wp,
                         float* __restrict__ out)
{
    int tIdx = blockIdx.x * blockDim.x + threadIdx.x;
    int i    = tIdx >> 5;          // point
    int c4g  = tIdx & 31;          // float4 group within 128 channels
    if (i >= N_PTS) return;

    int4 cd = *reinterpret_cast<const int4*>(&coords[(size_t)i * 4]);
    int vid = vid_of(cd);
    float fx = (float)cd.x, fy = (float)cd.y, fz = (float)cd.z;

    const float4* Wp4 = (const float4*)Wp;
    float4 w0 = Wp4[c4g];
    float4 w1 = Wp4[32 + c4g];
    float4 w2 = Wp4[64 + c4g];

    const float4* a = (const float4*)g_agg + (size_t)vid * 64;
    float4 ac = a[c4g];
    float4 as = a[32 + c4g];

    float4 o;
    float sn, cs;
    sincos_red(fx * w0.x + fy * w1.x + fz * w2.x, &sn, &cs);
    o.x = ac.x * cs + as.x * sn;
    sincos_red(fx * w0.y + fy * w1.y + fz * w2.y, &sn, &cs);
    o.y = ac.y * cs + as.y * sn;
    sincos_red(fx * w0.z + fy * w1.z + fz * w2.z, &sn, &cs);
    o.z = ac.z * cs + as.z * sn;
    sincos_red(fx * w0.w + fy * w1.w + fz * w2.w, &sn, &cs);
    o.w = ac.w * cs + as.w * sn;

    ((float4*)out)[(size_t)i * 32 + c4g] = o;
}

// ---------------------------------------------------------------------------
// Launch (k_gemm_ln_scatter is the 4th launch -> ncu capture slot)
// ---------------------------------------------------------------------------
extern "C" void kernel_launch(void* const* d_in, const int* in_sizes, int n_in,
                              void* d_out, int out_size)
{
    const float* x      = (const float*)d_in[0];
    const int*   coords = (const int*)  d_in[1];
    const float* Wm     = (const float*)d_in[2];
    const float* gamma  = (const float*)d_in[3];
    const float* beta   = (const float*)d_in[4];
    const float* Wp     = (const float*)d_in[5];
    float* out = (float*)d_out;

    cudaFuncSetAttribute(k_gemm_ln_scatter,
                         cudaFuncAttributeMaxDynamicSharedMemorySize, SMEM_BYTES);

    k_wsplit<<<(128 * 64 + 255) / 256, 256>>>(Wm);                 // 1
    k_zero_a<<<(HALF_GRID4 + 255) / 256, 256>>>();                 // 2
    k_zero_b<<<(HALF_GRID4 + 255) / 256, 256>>>();                 // 3
    k_gemm_ln_scatter<<<GRID_PERSIST, 256, SMEM_BYTES>>>(          // 4 <- ncu
        x, coords, gamma, beta, Wp);
    k_box_yz<<<NCELLS / 4, 256>>>();                               // 5
    k_box_x_div<<<NCELLS / 4, 256>>>();                            // 6
    k_gather<<<(N_PTS * 32 + 255) / 256, 256>>>(coords, Wp, out);  // 7
}

// round 15
// speedup vs baseline: 1.2352x; 1.2352x over previous
#include <cuda_runtime.h>
#include <cuda_fp16.h>
#include <cstdint>

// Problem constants (fixed by the dataset)
#define N_PTS   300000
#define INC     128
#define BATCH   4
#define GXD     50
#define GYD     50
#define GZD     4
#define NCELLS  40000          // BATCH*GXD*GYD*GZD
#define NFCH    256            // 2*INC feature channels (cos | sin)

// Scratch (static device globals — no allocation allowed)
__device__ float    g_grid[NCELLS * NFCH];  // scatter target [cell][256]
__device__ float    g_cnt [NCELLS];         // per-cell point count
__device__ float    g_tmp [NCELLS * NFCH];  // y/z box-summed features
__device__ float    g_tmpc[NCELLS];         // y/z box-summed counts
__device__ float    g_agg [NCELLS * NFCH];  // final per-cell averages
__device__ uint32_t g_WHi[128 * 64];        // W fp16 (packed half2 words)

__device__ __forceinline__ int vid_of(int4 cd) {
    return ((cd.w * GXD + (cd.x >> 3)) * GYD + (cd.y >> 3)) * GZD + (cd.z >> 3);
}

// sin/cos: explicit range reduction into [-pi, pi], then HW MUFU intrinsics.
__device__ __forceinline__ void sincos_red(float x, float* s, float* c) {
    float r = x - 6.283185307179586f * rintf(x * 0.15915494309189535f);
    *s = __sinf(r);
    *c = __cosf(r);
}

// Vectorized float4 reduction (PTX ISA 8.1, sm_90+ base feature)
__device__ __forceinline__ void red_add_v4(float* p, float4 v) {
    asm volatile("red.global.add.v4.f32 [%0], {%1, %2, %3, %4};"
                 :: "l"(p), "f"(v.x), "f"(v.y), "f"(v.z), "f"(v.w) : "memory");
}

// split (v0,v1) into packed half2 hi + half2 lo
__device__ __forceinline__ void cvt_split(float v0, float v1,
                                          uint32_t& hi, uint32_t& lo) {
    __half h0 = __float2half_rn(v0);
    __half h1 = __float2half_rn(v1);
    __half l0 = __float2half_rn(v0 - __half2float(h0));
    __half l1 = __float2half_rn(v1 - __half2float(h1));
    hi = ((uint32_t)__half_as_ushort(h1) << 16) | __half_as_ushort(h0);
    lo = ((uint32_t)__half_as_ushort(l1) << 16) | __half_as_ushort(l0);
}

__device__ __forceinline__ uint32_t smem_u32(const void* p) {
    return (uint32_t)__cvta_generic_to_shared(p);
}

// ldmatrix x4 (sm_75+): four 8x8 b16 matrices, lane-address groups of 8.
__device__ __forceinline__ void ldsm_x4(uint32_t* r, uint32_t addr) {
    asm volatile("ldmatrix.sync.aligned.m8n8.x4.shared.b16 {%0,%1,%2,%3}, [%4];"
                 : "=r"(r[0]), "=r"(r[1]), "=r"(r[2]), "=r"(r[3]) : "r"(addr));
}

// ---------------------------------------------------------------------------
// KW: one-shot fp16 pack of W (128x128) into packed half2 words
// ---------------------------------------------------------------------------
__global__ void k_wsplit(const float* __restrict__ Wm) {
    int i = blockIdx.x * blockDim.x + threadIdx.x;   // word index 0..8191
    if (i >= 128 * 64) return;
    int row = i >> 6, c2 = i & 63;
    const float2 v = *reinterpret_cast<const float2*>(Wm + (size_t)row * 128 + 2 * c2);
    __half h0 = __float2half_rn(v.x);
    __half h1 = __float2half_rn(v.y);
    g_WHi[i] = ((uint32_t)__half_as_ushort(h1) << 16) | __half_as_ushort(h0);
}

// ---------------------------------------------------------------------------
// K0a/K0b: zero the scatter grid + counts (split so GEMM is 4th launch)
// ---------------------------------------------------------------------------
#define HALF_GRID4 ((NCELLS * NFCH) / 8)     // float4 count of half the grid
__global__ void k_zero_a() {
    int i = blockIdx.x * blockDim.x + threadIdx.x;
    if (i < HALF_GRID4)
        reinterpret_cast<float4*>(g_grid)[i] = make_float4(0.f, 0.f, 0.f, 0.f);
}
__global__ void k_zero_b() {
    int i = blockIdx.x * blockDim.x + threadIdx.x;
    float4 z = make_float4(0.f, 0.f, 0.f, 0.f);
    if (i < HALF_GRID4) reinterpret_cast<float4*>(g_grid)[HALF_GRID4 + i] = z;
    if (i < NCELLS / 4) reinterpret_cast<float4*>(g_cnt)[i] = z;
}

// ---------------------------------------------------------------------------
// K1: PERSISTENT fused fp16x2-split mma.sync GEMM (ldmatrix loads) +
//     LayerNorm + sincos + red.v4 scatter. 296 CTAs (2/SM), 256 threads.
//     Split: h = x_hi*W_h16 + x_lo*W_h16  (dropped x*W_lo term ~1.4e-4 rel,
//     threshold is 1e-3). Warp tile 32x32 (wr=w>>2, nc=w&3).
//     Two-phase epilogue keeps Hs at 32 KB -> smem 76.0 KB -> 2 CTAs/SM.
// ---------------------------------------------------------------------------
#define LDA   136                       // halves per smem row (8-half pad)
#define A_TILE_BYTES (64  * LDA * 2)    // 17408
#define B_TILE_BYTES (128 * LDA * 2)    // 34816

#define OFF_B_HI  0
#define OFF_R     (OFF_B_HI + B_TILE_BYTES)      // 34816: region R (34816 B)
#define OFF_A_HI  OFF_R
#define OFF_A_LO  (OFF_A_HI + A_TILE_BYTES)      // 52224
#define OFF_HS    OFF_R                          // Hs[32][256] f32 = 32768 B
#define OFF_COORD (OFF_R + A_TILE_BYTES * 2)     // 69632: int4[64] = 1024
#define OFF_VID   (OFF_COORD + 1024)             // 70656: int[64] = 256
#define OFF_GB    (OFF_VID + 256)                // 70912: float2[128] = 1024
#define OFF_WP4   (OFF_GB + 1024)                // 71936: float4[128] = 2048
#define OFF_PS    (OFF_WP4 + 2048)               // 73984: 2 x [64][4] = 2048
#define SMEM_BYTES (OFF_PS + 2048)               // 76032 -> 2 CTAs/SM

#define GRID_PERSIST 296

__device__ __forceinline__ void mma16816(float* c,
                                         uint32_t a0, uint32_t a1,
                                         uint32_t a2, uint32_t a3,
                                         uint32_t b0, uint32_t b1) {
    asm volatile(
        "mma.sync.aligned.m16n8k16.row.col.f32.f16.f16.f32 "
        "{%0,%1,%2,%3}, {%4,%5,%6,%7}, {%8,%9}, {%0,%1,%2,%3};"
        : "+f"(c[0]), "+f"(c[1]), "+f"(c[2]), "+f"(c[3])
        : "r"(a0), "r"(a1), "r"(a2), "r"(a3), "r"(b0), "r"(b1));
}

__global__ void __launch_bounds__(256, 2)
k_gemm_ln_scatter(const float* __restrict__ x,
                  const int*   __restrict__ coords,
                  const float* __restrict__ gamma,
                  const float* __restrict__ beta,
                  const float* __restrict__ Wp)
{
    extern __shared__ char smraw[];
    __half* BsHi = (__half*)(smraw + OFF_B_HI);
    __half* AsHi = (__half*)(smraw + OFF_A_HI);
    __half* AsLo = (__half*)(smraw + OFF_A_LO);
    int4*   sCd  = (int4*)  (smraw + OFF_COORD);
    int*    sVid = (int*)   (smraw + OFF_VID);
    float2* sGB  = (float2*)(smraw + OFF_GB);
    float4* sWp4 = (float4*)(smraw + OFF_WP4);
    float*  sPS  = (float*) (smraw + OFF_PS);        // [64][4] partial sums
    float*  sPQ  = (float*) (smraw + OFF_PS + 1024); // [64][4] partial sqsums
    float*  Hs   = (float*) (smraw + OFF_HS);        // [32][256] per phase
    float4* Hs4  = (float4*)(smraw + OFF_HS);

    const int tid = threadIdx.x;

    // ---- One-time: stage W (uint2 = 8 halves per iter) + packed params ----
    {
        const uint2* whi = (const uint2*)g_WHi;
        #pragma unroll
        for (int it = 0; it < 16; it++) {
            int i2  = it * 256 + tid;          // 0..4095
            int row = i2 >> 5, c4 = i2 & 31;   // 32 uint2 per row (128 halves)
            *(uint2*)(BsHi + row * LDA + 4 * c4) = whi[i2];
        }
        if (tid < 128) {
            sGB[tid]  = make_float2(gamma[tid], beta[tid]);
            sWp4[tid] = make_float4(Wp[tid], Wp[128 + tid], Wp[256 + tid], 0.f);
        }
    }

    const int w    = tid >> 5;       // 0..7
    const int lane = tid & 31;
    const int g    = lane >> 2;      // groupID
    const int t    = lane & 3;       // thread-in-group
    const int wr   = w >> 2;         // row group 0..1 (32 rows each)
    const int nc   = w & 3;          // col group 0..3 (32 cols each)
    const int w32  = wr * 32;
    const int nt0  = nc * 4;         // first n-tile (8-col tiles)

    // ---- ldmatrix per-lane byte offsets (within a tile, k16 = 0) ----
    const int lq = lane & 7;
    uint32_t aoff[2];
    #pragma unroll
    for (int m = 0; m < 2; m++) {
        int row = w32 + m * 16 + lq + ((lane >> 3) & 1) * 8;
        int col = ((lane >> 4) & 1) * 8;
        aoff[m] = (uint32_t)((row * LDA + col) * 2);
    }
    uint32_t boff[2];
    #pragma unroll
    for (int p = 0; p < 2; p++) {
        int row = (nt0 + 2 * p + (lane >> 4)) * 8 + lq;
        int col = ((lane >> 3) & 1) * 8;
        boff[p] = (uint32_t)((row * LDA + col) * 2);
    }
    const uint32_t aHiB = smem_u32(AsHi), aLoB = smem_u32(AsLo);
    const uint32_t bHiB = smem_u32(BsHi);

    const int n_tiles = (N_PTS + 63) / 64;

    for (int tile = blockIdx.x; tile < n_tiles; tile += GRID_PERSIST) {
        const int row0 = tile * 64;
        __syncthreads();   // previous tile's scatter reads of Hs are done

        // ---- Stage x tile into A (inside region R): 4 threads per row ----
        {
            int row = tid >> 2, sel = tid & 3;     // row 0..63
            int gr = row0 + row;
            if (gr < N_PTS) {
                const float4* xrow = (const float4*)(x + (size_t)gr * 128) + sel * 8;
                #pragma unroll
                for (int q = 0; q < 8; q++) {
                    float4 v = xrow[q];
                    int c = sel * 32 + q * 4;
                    uint32_t hi, lo;
                    cvt_split(v.x, v.y, hi, lo);
                    *(uint32_t*)(AsHi + row * LDA + c)     = hi;
                    *(uint32_t*)(AsLo + row * LDA + c)     = lo;
                    cvt_split(v.z, v.w, hi, lo);
                    *(uint32_t*)(AsHi + row * LDA + c + 2) = hi;
                    *(uint32_t*)(AsLo + row * LDA + c + 2) = lo;
                }
            } else {
                #pragma unroll
                for (int q = 0; q < 8; q++) {
                    int c = sel * 32 + q * 4;
                    *(uint32_t*)(AsHi + row * LDA + c)     = 0u;
                    *(uint32_t*)(AsLo + row * LDA + c)     = 0u;
                    *(uint32_t*)(AsHi + row * LDA + c + 2) = 0u;
                    *(uint32_t*)(AsLo + row * LDA + c + 2) = 0u;
                }
            }
        }
        if (tid < 64) {
            int gr = row0 + tid;
            int4 cd = (gr < N_PTS) ? *reinterpret_cast<const int4*>(&coords[(size_t)gr * 4])
                                   : make_int4(0, 0, 0, 0);
            sCd[tid]  = cd;
            sVid[tid] = vid_of(cd);
        }
        __syncthreads();

        // ---- Warp-tiled fused mainloop (ldmatrix loads, 2-pass split) ----
        float acc[2][4][4];              // [m-group][n-tile][frag]
        #pragma unroll
        for (int m = 0; m < 2; m++)
            #pragma unroll
            for (int nt = 0; nt < 4; nt++)
                #pragma unroll
                for (int j = 0; j < 4; j++) acc[m][nt][j] = 0.f;

        #pragma unroll 2
        for (int k16 = 0; k16 < 8; k16++) {
            const uint32_t kb = (uint32_t)(k16 * 32);   // 16 halves = 32 bytes
            uint32_t ah[2][4], al[2][4], bh[2][4];
            #pragma unroll
            for (int m = 0; m < 2; m++) {
                ldsm_x4(ah[m], aHiB + aoff[m] + kb);
                ldsm_x4(al[m], aLoB + aoff[m] + kb);
            }
            #pragma unroll
            for (int p = 0; p < 2; p++) {
                ldsm_x4(bh[p], bHiB + boff[p] + kb);
            }
            #pragma unroll
            for (int p = 0; p < 2; p++) {
                #pragma unroll
                for (int j = 0; j < 2; j++) {
                    const int nt = 2 * p + j;
                    const uint32_t b0h = bh[p][2 * j], b1h = bh[p][2 * j + 1];
                    #pragma unroll
                    for (int m = 0; m < 2; m++) {
                        mma16816(acc[m][nt], ah[m][0], ah[m][1], ah[m][2], ah[m][3], b0h, b1h);
                        mma16816(acc[m][nt], al[m][0], al[m][1], al[m][2], al[m][3], b0h, b1h);
                    }
                }
            }
        }
        __syncthreads();   // done reading A; Hs may overwrite it

        // ---- LayerNorm stats: 32-col partials, combine across col groups ----
        float ps[2][2], pq[2][2];
        #pragma unroll
        for (int m = 0; m < 2; m++) {
            float s0 = 0.f, q0 = 0.f, s1 = 0.f, q1 = 0.f;
            #pragma unroll
            for (int nt = 0; nt < 4; nt++) {
                s0 += acc[m][nt][0] + acc[m][nt][1];
                q0 += acc[m][nt][0] * acc[m][nt][0] + acc[m][nt][1] * acc[m][nt][1];
                s1 += acc[m][nt][2] + acc[m][nt][3];
                q1 += acc[m][nt][2] * acc[m][nt][2] + acc[m][nt][3] * acc[m][nt][3];
            }
            #pragma unroll
            for (int off = 1; off <= 2; off <<= 1) {
                s0 += __shfl_xor_sync(0xffffffffu, s0, off);
                q0 += __shfl_xor_sync(0xffffffffu, q0, off);
                s1 += __shfl_xor_sync(0xffffffffu, s1, off);
                q1 += __shfl_xor_sync(0xffffffffu, q1, off);
            }
            ps[m][0] = s0; pq[m][0] = q0;
            ps[m][1] = s1; pq[m][1] = q1;
        }
        if (t == 0) {
            #pragma unroll
            for (int m = 0; m < 2; m++) {
                int r0 = w32 + m * 16 + g;
                sPS[r0 * 4 + nc]       = ps[m][0];  sPQ[r0 * 4 + nc]       = pq[m][0];
                sPS[(r0 + 8) * 4 + nc] = ps[m][1];  sPQ[(r0 + 8) * 4 + nc] = pq[m][1];
            }
        }
        __syncthreads();

        float mu[2][2], rs[2][2];
        #pragma unroll
        for (int m = 0; m < 2; m++)
            #pragma unroll
            for (int i = 0; i < 2; i++) {
                int r = w32 + m * 16 + g + i * 8;
                float4 s4 = *(const float4*)(sPS + r * 4);
                float4 q4 = *(const float4*)(sPQ + r * 4);
                float s = s4.x + s4.y + s4.z + s4.w;
                float q = q4.x + q4.y + q4.z + q4.w;
                float m0 = s * (1.f / 128.f);
                float v0 = q * (1.f / 128.f) - m0 * m0;
                mu[m][i] = m0;
                rs[m][i] = rsqrtf(v0 + 1e-6f);
            }

        // Count channel: one atomic per point
        if (tid < 64 && row0 + tid < N_PTS)
            atomicAdd(&g_cnt[sVid[tid]], 1.0f);

        // ---- Two-phase epilogue + scatter (Hs holds 32 rows per phase) ----
        #pragma unroll 1
        for (int h = 0; h < 2; h++) {
            if (wr == h) {
                #pragma unroll
                for (int m = 0; m < 2; m++) {
                    #pragma unroll
                    for (int i = 0; i < 2; i++) {
                        int rl = m * 16 + g + i * 8;         // 0..31
                        int r  = h * 32 + rl;                // tile row
                        int4 cd = sCd[r];
                        float fx = (float)cd.x, fy = (float)cd.y, fz = (float)cd.z;
                        float muv = mu[m][i], rsv = rs[m][i];
                        #pragma unroll
                        for (int nt = 0; nt < 4; nt++) {
                            int c0 = (nt0 + nt) * 8 + 2 * t;
                            float2 gb0 = sGB[c0], gb1 = sGB[c0 + 1];
                            float4 wv0 = sWp4[c0], wv1 = sWp4[c0 + 1];
                            float h0 = (acc[m][nt][2 * i]     - muv) * rsv * gb0.x + gb0.y;
                            float h1 = (acc[m][nt][2 * i + 1] - muv) * rsv * gb1.x + gb1.y;
                            float sn0, cs0, sn1, cs1;
                            sincos_red(fx * wv0.x + fy * wv0.y + fz * wv0.z, &sn0, &cs0);
                            sincos_red(fx * wv1.x + fy * wv1.y + fz * wv1.z, &sn1, &cs1);
                            {
                                float2 pr = make_float2(h0 * cs0, h1 * cs1);
                                *(float2*)(Hs + rl * 256 + ((((c0 >> 2) + rl) & 63) << 2) + (c0 & 3)) = pr;
                            }
                            {
                                int cx = c0 + 128;
                                float2 pr = make_float2(h0 * sn0, h1 * sn1);
                                *(float2*)(Hs + rl * 256 + ((((cx >> 2) + rl) & 63) << 2) + (cx & 3)) = pr;
                            }
                        }
                    }
                }
            }
            __syncthreads();

            // Scatter 32 points: warp w handles local rows w*4 .. w*4+3
            for (int i = 0; i < 4; i++) {
                int pl = w * 4 + i;              // local row 0..31
                int gp = row0 + h * 32 + pl;
                if (gp >= N_PTS) break;          // warp-uniform
                float* gc = g_grid + (size_t)sVid[h * 32 + pl] * NFCH;
                float4 v0 = Hs4[pl * 64 + ((lane + pl) & 63)];
                float4 v1 = Hs4[pl * 64 + ((lane + 32 + pl) & 63)];
                red_add_v4(gc + 4 * lane,       v0);
                red_add_v4(gc + 128 + 4 * lane, v1);
            }
            __syncthreads();   // scatter reads done before next phase writes Hs
        }
    }
}

// ---------------------------------------------------------------------------
// K2a: 9-point box sum over (y,z), float4 channels. 4 cells per 256-thr block.
// ---------------------------------------------------------------------------
__global__ void k_box_yz() {
    int cell = blockIdx.x * 4 + (threadIdx.x >> 6);
    int ch4  = threadIdx.x & 63;
    int rem  = cell % (GYD * GZD);
    int cy   = rem / GZD;
    int cz   = rem % GZD;
    int dylo = (cy > 0) ? -1 : 0, dyhi = (cy < GYD - 1) ? 1 : 0;
    int dzlo = (cz > 0) ? -1 : 0, dzhi = (cz < GZD - 1) ? 1 : 0;

    const float4* grid4 = (const float4*)g_grid;
    float4 s = make_float4(0.f, 0.f, 0.f, 0.f);
    float  sc = 0.f;
    for (int dy = dylo; dy <= dyhi; dy++)
        for (int dz = dzlo; dz <= dzhi; dz++) {
            int nb = cell + dy * GZD + dz;
            float4 v = grid4[(size_t)nb * 64 + ch4];
            s.x += v.x; s.y += v.y; s.z += v.z; s.w += v.w;
            if (ch4 == 0) sc += g_cnt[nb];
        }
    ((float4*)g_tmp)[(size_t)cell * 64 + ch4] = s;
    if (ch4 == 0) g_tmpc[cell] = sc;
}

// ---------------------------------------------------------------------------
// K2b: 3-point sum over x + divide by count. 4 cells per 256-thread block.
// ---------------------------------------------------------------------------
__global__ void k_box_x_div() {
    int cell = blockIdx.x * 4 + (threadIdx.x >> 6);
    int ch4  = threadIdx.x & 63;
    int cx   = (cell % (GXD * GYD * GZD)) / (GYD * GZD);

    const float4* tmp4 = (const float4*)g_tmp;
    float4 num = make_float4(0.f, 0.f, 0.f, 0.f);
    float  den = 0.f;
    #pragma unroll
    for (int dx = -1; dx <= 1; dx++) {
        int xx = cx + dx;
        if (xx < 0 || xx >= GXD) continue;
        int nb = cell + dx * GYD * GZD;
        float4 v = tmp4[(size_t)nb * 64 + ch4];
        num.x += v.x; num.y += v.y; num.z += v.z; num.w += v.w;
        den += g_tmpc[nb];
    }
    float inv = 1.0f / fmaxf(den, 1e-12f);
    float4 r = make_float4(num.x * inv, num.y * inv, num.z * inv, num.w * inv);
    ((float4*)g_agg)[(size_t)cell * 64 + ch4] = r;
}

// ---------------------------------------------------------------------------
// K3: gather + recombine, float4: warp per point, lane = float4 group (c4g)
// ---------------------------------------------------------------------------
__global__ void k_gather(const int* __restrict__ coords,
                         const float* __restrict__ Wp,
                         float* __restrict__ out)
{
    int tIdx = blockIdx.x * blockDim.x + threadIdx.x;
    int i    = tIdx >> 5;          // point
    int c4g  = tIdx & 31;          // float4 group within 128 channels
    if (i >= N_PTS) return;

    int4 cd = *reinterpret_cast<const int4*>(&coords[(size_t)i * 4]);
    int vid = vid_of(cd);
    float fx = (float)cd.x, fy = (float)cd.y, fz = (float)cd.z;

    const float4* Wp4 = (const float4*)Wp;
    float4 w0 = Wp4[c4g];
    float4 w1 = Wp4[32 + c4g];
    float4 w2 = Wp4[64 + c4g];

    const float4* a = (const float4*)g_agg + (size_t)vid * 64;
    float4 ac = a[c4g];
    float4 as = a[32 + c4g];

    float4 o;
    float sn, cs;
    sincos_red(fx * w0.x + fy * w1.x + fz * w2.x, &sn, &cs);
    o.x = ac.x * cs + as.x * sn;
    sincos_red(fx * w0.y + fy * w1.y + fz * w2.y, &sn, &cs);
    o.y = ac.y * cs + as.y * sn;
    sincos_red(fx * w0.z + fy * w1.z + fz * w2.z, &sn, &cs);
    o.z = ac.z * cs + as.z * sn;
    sincos_red(fx * w0.w + fy * w1.w + fz * w2.w, &sn, &cs);
    o.w = ac.w * cs + as.w * sn;

    ((float4*)out)[(size_t)i * 32 + c4g] = o;
}

// ---------------------------------------------------------------------------
// Launch (k_gemm_ln_scatter is the 4th launch -> ncu capture slot)
// ---------------------------------------------------------------------------
extern "C" void kernel_launch(void* const* d_in, const int* in_sizes, int n_in,
                              void* d_out, int out_size)
{
    const float* x      = (const float*)d_in[0];
    const int*   coords = (const int*)  d_in[1];
    const float* Wm     = (const float*)d_in[2];
    const float* gamma  = (const float*)d_in[3];
    const float* beta   = (const float*)d_in[4];
    const float* Wp     = (const float*)d_in[5];
    float* out = (float*)d_out;

    cudaFuncSetAttribute(k_gemm_ln_scatter,
                         cudaFuncAttributeMaxDynamicSharedMemorySize, SMEM_BYTES);

    k_wsplit<<<(128 * 64 + 255) / 256, 256>>>(Wm);                 // 1
    k_zero_a<<<(HALF_GRID4 + 255) / 256, 256>>>();                 // 2
    k_zero_b<<<(HALF_GRID4 + 255) / 256, 256>>>();                 // 3
    k_gemm_ln_scatter<<<GRID_PERSIST, 256, SMEM_BYTES>>>(          // 4 <- ncu
        x, coords, gamma, beta, Wp);
    k_box_yz<<<NCELLS / 4, 256>>>();                               // 5
    k_box_x_div<<<NCELLS / 4, 256>>>();                            // 6
    k_gather<<<(N_PTS * 32 + 255) / 256, 256>>>(coords, Wp, out);  // 7
}

// round 16
// speedup vs baseline: 1.4298x; 1.1575x over previous
#include <cuda_runtime.h>
#include <cuda_fp16.h>
#include <cstdint>

// Problem constants (fixed by the dataset)
#define N_PTS   300000
#define INC     128
#define BATCH   4
#define GXD     50
#define GYD     50
#define GZD     4
#define NCELLS  40000          // BATCH*GXD*GYD*GZD
#define NFCH    256            // 2*INC feature channels (cos | sin)

// Scratch (static device globals — no allocation allowed)
__device__ float    g_grid[NCELLS * NFCH];  // scatter target [cell][256]
__device__ float    g_cnt [NCELLS];         // per-cell point count
__device__ float    g_tmp [NCELLS * NFCH];  // y/z box-summed features
__device__ float    g_tmpc[NCELLS];         // y/z box-summed counts
__device__ float    g_agg [NCELLS * NFCH];  // final per-cell averages
__device__ uint32_t g_WHi[128 * 64];        // W fp16 (packed half2 words)

__device__ __forceinline__ int vid_of(int4 cd) {
    return ((cd.w * GXD + (cd.x >> 3)) * GYD + (cd.y >> 3)) * GZD + (cd.z >> 3);
}

// sin/cos: explicit range reduction into [-pi, pi], then HW MUFU intrinsics.
__device__ __forceinline__ void sincos_red(float x, float* s, float* c) {
    float r = x - 6.283185307179586f * rintf(x * 0.15915494309189535f);
    *s = __sinf(r);
    *c = __cosf(r);
}

// Vectorized float4 reduction (PTX ISA 8.1, sm_90+ base feature)
__device__ __forceinline__ void red_add_v4(float* p, float4 v) {
    asm volatile("red.global.add.v4.f32 [%0], {%1, %2, %3, %4};"
                 :: "l"(p), "f"(v.x), "f"(v.y), "f"(v.z), "f"(v.w) : "memory");
}

// split (v0,v1) into packed half2 hi + half2 lo
__device__ __forceinline__ void cvt_split(float v0, float v1,
                                          uint32_t& hi, uint32_t& lo) {
    __half h0 = __float2half_rn(v0);
    __half h1 = __float2half_rn(v1);
    __half l0 = __float2half_rn(v0 - __half2float(h0));
    __half l1 = __float2half_rn(v1 - __half2float(h1));
    hi = ((uint32_t)__half_as_ushort(h1) << 16) | __half_as_ushort(h0);
    lo = ((uint32_t)__half_as_ushort(l1) << 16) | __half_as_ushort(l0);
}

__device__ __forceinline__ uint32_t smem_u32(const void* p) {
    return (uint32_t)__cvta_generic_to_shared(p);
}

// ldmatrix x4 (sm_75+): four 8x8 b16 matrices, lane-address groups of 8.
__device__ __forceinline__ void ldsm_x4(uint32_t* r, uint32_t addr) {
    asm volatile("ldmatrix.sync.aligned.m8n8.x4.shared.b16 {%0,%1,%2,%3}, [%4];"
                 : "=r"(r[0]), "=r"(r[1]), "=r"(r[2]), "=r"(r[3]) : "r"(addr));
}

// cp.async helpers (sm_80+ base): 16B copy with zero-fill via src-size.
__device__ __forceinline__ void cpa_cg16(uint32_t dst, const void* src, int sz) {
    asm volatile("cp.async.cg.shared.global [%0], [%1], 16, %2;"
                 :: "r"(dst), "l"(src), "r"(sz));
}
__device__ __forceinline__ void cpa_commit() {
    asm volatile("cp.async.commit_group;");
}
__device__ __forceinline__ void cpa_wait0() {
    asm volatile("cp.async.wait_group 0;" ::: "memory");
}

// ---------------------------------------------------------------------------
// KW: one-shot fp16 pack of W (128x128) into packed half2 words
// ---------------------------------------------------------------------------
__global__ void k_wsplit(const float* __restrict__ Wm) {
    int i = blockIdx.x * blockDim.x + threadIdx.x;   // word index 0..8191
    if (i >= 128 * 64) return;
    int row = i >> 6, c2 = i & 63;
    const float2 v = *reinterpret_cast<const float2*>(Wm + (size_t)row * 128 + 2 * c2);
    __half h0 = __float2half_rn(v.x);
    __half h1 = __float2half_rn(v.y);
    g_WHi[i] = ((uint32_t)__half_as_ushort(h1) << 16) | __half_as_ushort(h0);
}

// ---------------------------------------------------------------------------
// K0a/K0b: zero the scatter grid + counts (split so GEMM is 4th launch)
// ---------------------------------------------------------------------------
#define HALF_GRID4 ((NCELLS * NFCH) / 8)     // float4 count of half the grid
__global__ void k_zero_a() {
    int i = blockIdx.x * blockDim.x + threadIdx.x;
    if (i < HALF_GRID4)
        reinterpret_cast<float4*>(g_grid)[i] = make_float4(0.f, 0.f, 0.f, 0.f);
}
__global__ void k_zero_b() {
    int i = blockIdx.x * blockDim.x + threadIdx.x;
    float4 z = make_float4(0.f, 0.f, 0.f, 0.f);
    if (i < HALF_GRID4) reinterpret_cast<float4*>(g_grid)[HALF_GRID4 + i] = z;
    if (i < NCELLS / 4) reinterpret_cast<float4*>(g_cnt)[i] = z;
}

// ---------------------------------------------------------------------------
// K1: PERSISTENT fused fp16x2-split mma.sync GEMM (ldmatrix loads) +
//     LayerNorm + sincos + red.v4 scatter, with cp.async DOUBLE-BUFFERED
//     x/coords prefetch (next tile's gmem loads fly during this tile's
//     mainloop+epilogue). 296 CTAs (2/SM), 256 threads.
//     Warp tile 32x32 (wr=w>>2, nc=w&3). smem ~107 KB -> 2 CTAs/SM.
// ---------------------------------------------------------------------------
#define LDA   136                       // halves per smem row (8-half pad)
#define A_TILE_BYTES (64  * LDA * 2)    // 17408
#define B_TILE_BYTES (128 * LDA * 2)    // 34816

#define OFF_B_HI  0
#define OFF_R     (OFF_B_HI + B_TILE_BYTES)      // 34816: region R (34816 B)
#define OFF_A_HI  OFF_R
#define OFF_A_LO  (OFF_A_HI + A_TILE_BYTES)      // 52224
#define OFF_HS    OFF_R                          // Hs[32][256] f32 = 32768 B
#define OFF_COORD (OFF_R + A_TILE_BYTES * 2)     // 69632: int4[64] = 1024
#define OFF_VID   (OFF_COORD + 1024)             // 70656: int[64] = 256
#define OFF_GB    (OFF_VID + 256)                // 70912: float2[128] = 1024
#define OFF_WP4   (OFF_GB + 1024)                // 71936: float4[128] = 2048
#define OFF_PS    (OFF_WP4 + 2048)               // 73984: 2 x [64][4] = 2048
#define OFF_XS    (OFF_PS + 2048)                // 76032: raw x tile 32768 B
#define OFF_XC    (OFF_XS + 32768)               // 108800: coords prefetch 1024 B
#define SMEM_BYTES (OFF_XC + 1024)               // 109824 -> 2 CTAs/SM

#define GRID_PERSIST 296

__device__ __forceinline__ void mma16816(float* c,
                                         uint32_t a0, uint32_t a1,
                                         uint32_t a2, uint32_t a3,
                                         uint32_t b0, uint32_t b1) {
    asm volatile(
        "mma.sync.aligned.m16n8k16.row.col.f32.f16.f16.f32 "
        "{%0,%1,%2,%3}, {%4,%5,%6,%7}, {%8,%9}, {%0,%1,%2,%3};"
        : "+f"(c[0]), "+f"(c[1]), "+f"(c[2]), "+f"(c[3])
        : "r"(a0), "r"(a1), "r"(a2), "r"(a3), "r"(b0), "r"(b1));
}

__global__ void __launch_bounds__(256, 2)
k_gemm_ln_scatter(const float* __restrict__ x,
                  const int*   __restrict__ coords,
                  const float* __restrict__ gamma,
                  const float* __restrict__ beta,
                  const float* __restrict__ Wp)
{
    extern __shared__ char smraw[];
    __half* BsHi = (__half*)(smraw + OFF_B_HI);
    __half* AsHi = (__half*)(smraw + OFF_A_HI);
    __half* AsLo = (__half*)(smraw + OFF_A_LO);
    int4*   sCd  = (int4*)  (smraw + OFF_COORD);
    int*    sVid = (int*)   (smraw + OFF_VID);
    float2* sGB  = (float2*)(smraw + OFF_GB);
    float4* sWp4 = (float4*)(smraw + OFF_WP4);
    float*  sPS  = (float*) (smraw + OFF_PS);        // [64][4] partial sums
    float*  sPQ  = (float*) (smraw + OFF_PS + 1024); // [64][4] partial sqsums
    float*  Hs   = (float*) (smraw + OFF_HS);        // [32][256] per phase
    float4* Hs4  = (float4*)(smraw + OFF_HS);
    float4* XS4  = (float4*)(smraw + OFF_XS);        // raw x prefetch buffer
    int4*   XC   = (int4*)  (smraw + OFF_XC);        // coords prefetch buffer

    const int tid = threadIdx.x;
    const uint32_t xsB = smem_u32(XS4);
    const uint32_t xcB = smem_u32(XC);

    // ---- One-time: stage W (uint2 = 8 halves per iter) + packed params ----
    {
        const uint2* whi = (const uint2*)g_WHi;
        #pragma unroll
        for (int it = 0; it < 16; it++) {
            int i2  = it * 256 + tid;          // 0..4095
            int row = i2 >> 5, c4 = i2 & 31;   // 32 uint2 per row (128 halves)
            *(uint2*)(BsHi + row * LDA + 4 * c4) = whi[i2];
        }
        if (tid < 128) {
            sGB[tid]  = make_float2(gamma[tid], beta[tid]);
            sWp4[tid] = make_float4(Wp[tid], Wp[128 + tid], Wp[256 + tid], 0.f);
        }
    }

    const int w    = tid >> 5;       // 0..7
    const int lane = tid & 31;
    const int g    = lane >> 2;      // groupID
    const int t    = lane & 3;       // thread-in-group
    const int wr   = w >> 2;         // row group 0..1 (32 rows each)
    const int nc   = w & 3;          // col group 0..3 (32 cols each)
    const int w32  = wr * 32;
    const int nt0  = nc * 4;         // first n-tile (8-col tiles)

    // ---- ldmatrix per-lane byte offsets (within a tile, k16 = 0) ----
    const int lq = lane & 7;
    uint32_t aoff[2];
    #pragma unroll
    for (int m = 0; m < 2; m++) {
        int row = w32 + m * 16 + lq + ((lane >> 3) & 1) * 8;
        int col = ((lane >> 4) & 1) * 8;
        aoff[m] = (uint32_t)((row * LDA + col) * 2);
    }
    uint32_t boff[2];
    #pragma unroll
    for (int p = 0; p < 2; p++) {
        int row = (nt0 + 2 * p + (lane >> 4)) * 8 + lq;
        int col = ((lane >> 3) & 1) * 8;
        boff[p] = (uint32_t)((row * LDA + col) * 2);
    }
    const uint32_t aHiB = smem_u32(AsHi), aLoB = smem_u32(AsLo);
    const uint32_t bHiB = smem_u32(BsHi);

    const int n_tiles = (N_PTS + 63) / 64;

    // ---- Prefetch helper (inlined twice): tile's x + coords via cp.async ----
    // x: idx = q*256 + tid -> row = idx>>5, c4 = idx&31, dst lane-consecutive.
    // coords: tid<64 -> one int4. OOB rows: src-size 0 (zero-fill), clamped ptr.
    #define PREFETCH_TILE(row0p)                                               \
    do {                                                                       \
        _Pragma("unroll")                                                      \
        for (int q = 0; q < 8; q++) {                                          \
            int idx = q * 256 + tid;                                           \
            int row = idx >> 5, c4 = idx & 31;                                 \
            int gr = (row0p) + row;                                            \
            int ok = (gr < N_PTS);                                             \
            const float* src = x + (size_t)(ok ? gr : 0) * 128 + c4 * 4;       \
            cpa_cg16(xsB + (uint32_t)idx * 16, src, ok ? 16 : 0);              \
        }                                                                      \
        if (tid < 64) {                                                        \
            int gr = (row0p) + tid;                                            \
            int ok = (gr < N_PTS);                                             \
            const int* src = coords + (size_t)(ok ? gr : 0) * 4;               \
            cpa_cg16(xcB + (uint32_t)tid * 16, src, ok ? 16 : 0);              \
        }                                                                      \
        cpa_commit();                                                          \
    } while (0)

    // Prologue: prefetch first tile
    if (blockIdx.x < n_tiles) PREFETCH_TILE(blockIdx.x * 64);

    for (int tile = blockIdx.x; tile < n_tiles; tile += GRID_PERSIST) {
        const int row0 = tile * 64;
        cpa_wait0();
        __syncthreads();   // prev scatter reads done + prefetched data visible

        // ---- Convert XS (raw fp32) -> A hi/lo tiles; coords XC -> sCd/sVid --
        #pragma unroll
        for (int q = 0; q < 8; q++) {
            int idx = q * 256 + tid;           // row = q*8 + w, col4 = lane
            float4 v = XS4[idx];
            int row = q * 8 + w;
            int c = lane * 4;                  // halves column
            uint32_t h0, l0, h1, l1;
            cvt_split(v.x, v.y, h0, l0);
            cvt_split(v.z, v.w, h1, l1);
            *(uint2*)(AsHi + row * LDA + c) = make_uint2(h0, h1);
            *(uint2*)(AsLo + row * LDA + c) = make_uint2(l0, l1);
        }
        if (tid < 64) {
            int4 cd = XC[tid];
            sCd[tid]  = cd;
            sVid[tid] = vid_of(cd);
        }
        __syncthreads();   // XS/XC consumed, A ready

        // Prefetch next tile (lands in XS/XC during mainloop+epilogue)
        {
            int nxt = tile + GRID_PERSIST;
            if (nxt < n_tiles) PREFETCH_TILE(nxt * 64);
        }

        // ---- Warp-tiled fused mainloop (ldmatrix loads, 2-pass split) ----
        float acc[2][4][4];              // [m-group][n-tile][frag]
        #pragma unroll
        for (int m = 0; m < 2; m++)
            #pragma unroll
            for (int nt = 0; nt < 4; nt++)
                #pragma unroll
                for (int j = 0; j < 4; j++) acc[m][nt][j] = 0.f;

        #pragma unroll 2
        for (int k16 = 0; k16 < 8; k16++) {
            const uint32_t kb = (uint32_t)(k16 * 32);   // 16 halves = 32 bytes
            uint32_t ah[2][4], al[2][4], bh[2][4];
            #pragma unroll
            for (int m = 0; m < 2; m++) {
                ldsm_x4(ah[m], aHiB + aoff[m] + kb);
                ldsm_x4(al[m], aLoB + aoff[m] + kb);
            }
            #pragma unroll
            for (int p = 0; p < 2; p++) {
                ldsm_x4(bh[p], bHiB + boff[p] + kb);
            }
            #pragma unroll
            for (int p = 0; p < 2; p++) {
                #pragma unroll
                for (int j = 0; j < 2; j++) {
                    const int nt = 2 * p + j;
                    const uint32_t b0h = bh[p][2 * j], b1h = bh[p][2 * j + 1];
                    #pragma unroll
                    for (int m = 0; m < 2; m++) {
                        mma16816(acc[m][nt], ah[m][0], ah[m][1], ah[m][2], ah[m][3], b0h, b1h);
                        mma16816(acc[m][nt], al[m][0], al[m][1], al[m][2], al[m][3], b0h, b1h);
                    }
                }
            }
        }
        __syncthreads();   // done reading A; Hs may overwrite it

        // ---- LayerNorm stats: 32-col partials, combine across col groups ----
        float ps[2][2], pq[2][2];
        #pragma unroll
        for (int m = 0; m < 2; m++) {
            float s0 = 0.f, q0 = 0.f, s1 = 0.f, q1 = 0.f;
            #pragma unroll
            for (int nt = 0; nt < 4; nt++) {
                s0 += acc[m][nt][0] + acc[m][nt][1];
                q0 += acc[m][nt][0] * acc[m][nt][0] + acc[m][nt][1] * acc[m][nt][1];
                s1 += acc[m][nt][2] + acc[m][nt][3];
                q1 += acc[m][nt][2] * acc[m][nt][2] + acc[m][nt][3] * acc[m][nt][3];
            }
            #pragma unroll
            for (int off = 1; off <= 2; off <<= 1) {
                s0 += __shfl_xor_sync(0xffffffffu, s0, off);
                q0 += __shfl_xor_sync(0xffffffffu, q0, off);
                s1 += __shfl_xor_sync(0xffffffffu, s1, off);
                q1 += __shfl_xor_sync(0xffffffffu, q1, off);
            }
            ps[m][0] = s0; pq[m][0] = q0;
            ps[m][1] = s1; pq[m][1] = q1;
        }
        if (t == 0) {
            #pragma unroll
            for (int m = 0; m < 2; m++) {
                int r0 = w32 + m * 16 + g;
                sPS[r0 * 4 + nc]       = ps[m][0];  sPQ[r0 * 4 + nc]       = pq[m][0];
                sPS[(r0 + 8) * 4 + nc] = ps[m][1];  sPQ[(r0 + 8) * 4 + nc] = pq[m][1];
            }
        }
        __syncthreads();

        float mu[2][2], rs[2][2];
        #pragma unroll
        for (int m = 0; m < 2; m++)
            #pragma unroll
            for (int i = 0; i < 2; i++) {
                int r = w32 + m * 16 + g + i * 8;
                float4 s4 = *(const float4*)(sPS + r * 4);
                float4 q4 = *(const float4*)(sPQ + r * 4);
                float s = s4.x + s4.y + s4.z + s4.w;
                float q = q4.x + q4.y + q4.z + q4.w;
                float m0 = s * (1.f / 128.f);
                float v0 = q * (1.f / 128.f) - m0 * m0;
                mu[m][i] = m0;
                rs[m][i] = rsqrtf(v0 + 1e-6f);
            }

        // Count channel: one atomic per point
        if (tid < 64 && row0 + tid < N_PTS)
            atomicAdd(&g_cnt[sVid[tid]], 1.0f);

        // ---- Two-phase epilogue + scatter (Hs holds 32 rows per phase) ----
        #pragma unroll 1
        for (int h = 0; h < 2; h++) {
            if (wr == h) {
                #pragma unroll
                for (int m = 0; m < 2; m++) {
                    #pragma unroll
                    for (int i = 0; i < 2; i++) {
                        int rl = m * 16 + g + i * 8;         // 0..31
                        int r  = h * 32 + rl;                // tile row
                        int4 cd = sCd[r];
                        float fx = (float)cd.x, fy = (float)cd.y, fz = (float)cd.z;
                        float muv = mu[m][i], rsv = rs[m][i];
                        #pragma unroll
                        for (int nt = 0; nt < 4; nt++) {
                            int c0 = (nt0 + nt) * 8 + 2 * t;
                            float2 gb0 = sGB[c0], gb1 = sGB[c0 + 1];
                            float4 wv0 = sWp4[c0], wv1 = sWp4[c0 + 1];
                            float h0 = (acc[m][nt][2 * i]     - muv) * rsv * gb0.x + gb0.y;
                            float h1 = (acc[m][nt][2 * i + 1] - muv) * rsv * gb1.x + gb1.y;
                            float sn0, cs0, sn1, cs1;
                            sincos_red(fx * wv0.x + fy * wv0.y + fz * wv0.z, &sn0, &cs0);
                            sincos_red(fx * wv1.x + fy * wv1.y + fz * wv1.z, &sn1, &cs1);
                            {
                                float2 pr = make_float2(h0 * cs0, h1 * cs1);
                                *(float2*)(Hs + rl * 256 + ((((c0 >> 2) + rl) & 63) << 2) + (c0 & 3)) = pr;
                            }
                            {
                                int cx = c0 + 128;
                                float2 pr = make_float2(h0 * sn0, h1 * sn1);
                                *(float2*)(Hs + rl * 256 + ((((cx >> 2) + rl) & 63) << 2) + (cx & 3)) = pr;
                            }
                        }
                    }
                }
            }
            __syncthreads();

            // Scatter 32 points: warp w handles local rows w*4 .. w*4+3
            for (int i = 0; i < 4; i++) {
                int pl = w * 4 + i;              // local row 0..31
                int gp = row0 + h * 32 + pl;
                if (gp >= N_PTS) break;          // warp-uniform
                float* gc = g_grid + (size_t)sVid[h * 32 + pl] * NFCH;
                float4 v0 = Hs4[pl * 64 + ((lane + pl) & 63)];
                float4 v1 = Hs4[pl * 64 + ((lane + 32 + pl) & 63)];
                red_add_v4(gc + 4 * lane,       v0);
                red_add_v4(gc + 128 + 4 * lane, v1);
            }
            __syncthreads();   // scatter reads done before next phase writes Hs
        }
    }
}

// ---------------------------------------------------------------------------
// K2a: 9-point box sum over (y,z), float4 channels. 4 cells per 256-thr block.
// ---------------------------------------------------------------------------
__global__ void k_box_yz() {
    int cell = blockIdx.x * 4 + (threadIdx.x >> 6);
    int ch4  = threadIdx.x & 63;
    int rem  = cell % (GYD * GZD);
    int cy   = rem / GZD;
    int cz   = rem % GZD;
    int dylo = (cy > 0) ? -1 : 0, dyhi = (cy < GYD - 1) ? 1 : 0;
    int dzlo = (cz > 0) ? -1 : 0, dzhi = (cz < GZD - 1) ? 1 : 0;

    const float4* grid4 = (const float4*)g_grid;
    float4 s = make_float4(0.f, 0.f, 0.f, 0.f);
    float  sc = 0.f;
    for (int dy = dylo; dy <= dyhi; dy++)
        for (int dz = dzlo; dz <= dzhi; dz++) {
            int nb = cell + dy * GZD + dz;
            float4 v = grid4[(size_t)nb * 64 + ch4];
            s.x += v.x; s.y += v.y; s.z += v.z; s.w += v.w;
            if (ch4 == 0) sc += g_cnt[nb];
        }
    ((float4*)g_tmp)[(size_t)cell * 64 + ch4] = s;
    if (ch4 == 0) g_tmpc[cell] = sc;
}

// ---------------------------------------------------------------------------
// K2b: 3-point sum over x + divide by count. 4 cells per 256-thread block.
// ---------------------------------------------------------------------------
__global__ void k_box_x_div() {
    int cell = blockIdx.x * 4 + (threadIdx.x >> 6);
    int ch4  = threadIdx.x & 63;
    int cx   = (cell % (GXD * GYD * GZD)) / (GYD * GZD);

    const float4* tmp4 = (const float4*)g_tmp;
    float4 num = make_float4(0.f, 0.f, 0.f, 0.f);
    float  den = 0.f;
    #pragma unroll
    for (int dx = -1; dx <= 1; dx++) {
        int xx = cx + dx;
        if (xx < 0 || xx >= GXD) continue;
        int nb = cell + dx * GYD * GZD;
        float4 v = tmp4[(size_t)nb * 64 + ch4];
        num.x += v.x; num.y += v.y; num.z += v.z; num.w += v.w;
        den += g_tmpc[nb];
    }
    float inv = 1.0f / fmaxf(den, 1e-12f);
    float4 r = make_float4(num.x * inv, num.y * inv, num.z * inv, num.w * inv);
    ((float4*)g_agg)[(size_t)cell * 64 + ch4] = r;
}

// ---------------------------------------------------------------------------
// K3: gather + recombine, float4: warp per point, lane = float4 group (c4g)
// ---------------------------------------------------------------------------
__global__ void k_gather(const int* __restrict__ coords,
                         const float* __restrict__ Wp,
                         float* __restrict__ out)
{
    int tIdx = blockIdx.x * blockDim.x + threadIdx.x;
    int i    = tIdx >> 5;          // point
    int c4g  = tIdx & 31;          // float4 group within 128 channels
    if (i >= N_PTS) return;

    int4 cd = *reinterpret_cast<const int4*>(&coords[(size_t)i * 4]);
    int vid = vid_of(cd);
    float fx = (float)cd.x, fy = (float)cd.y, fz = (float)cd.z;

    const float4* Wp4 = (const float4*)Wp;
    float4 w0 = Wp4[c4g];
    float4 w1 = Wp4[32 + c4g];
    float4 w2 = Wp4[64 + c4g];

    const float4* a = (const float4*)g_agg + (size_t)vid * 64;
    float4 ac = a[c4g];
    float4 as = a[32 + c4g];

    float4 o;
    float sn, cs;
    sincos_red(fx * w0.x + fy * w1.x + fz * w2.x, &sn, &cs);
    o.x = ac.x * cs + as.x * sn;
    sincos_red(fx * w0.y + fy * w1.y + fz * w2.y, &sn, &cs);
    o.y = ac.y * cs + as.y * sn;
    sincos_red(fx * w0.z + fy * w1.z + fz * w2.z, &sn, &cs);
    o.z = ac.z * cs + as.z * sn;
    sincos_red(fx * w0.w + fy * w1.w + fz * w2.w, &sn, &cs);
    o.w = ac.w * cs + as.w * sn;

    ((float4*)out)[(size_t)i * 32 + c4g] = o;
}

// ---------------------------------------------------------------------------
// Launch (k_gemm_ln_scatter is the 4th launch -> ncu capture slot)
// ---------------------------------------------------------------------------
extern "C" void kernel_launch(void* const* d_in, const int* in_sizes, int n_in,
                              void* d_out, int out_size)
{
    const float* x      = (const float*)d_in[0];
    const int*   coords = (const int*)  d_in[1];
    const float* Wm     = (const float*)d_in[2];
    const float* gamma  = (const float*)d_in[3];
    const float* beta   = (const float*)d_in[4];
    const float* Wp     = (const float*)d_in[5];
    float* out = (float*)d_out;

    cudaFuncSetAttribute(k_gemm_ln_scatter,
                         cudaFuncAttributeMaxDynamicSharedMemorySize, SMEM_BYTES);

    k_wsplit<<<(128 * 64 + 255) / 256, 256>>>(Wm);                 // 1
    k_zero_a<<<(HALF_GRID4 + 255) / 256, 256>>>();                 // 2
    k_zero_b<<<(HALF_GRID4 + 255) / 256, 256>>>();                 // 3
    k_gemm_ln_scatter<<<GRID_PERSIST, 256, SMEM_BYTES>>>(          // 4 <- ncu
        x, coords, gamma, beta, Wp);
    k_box_yz<<<NCELLS / 4, 256>>>();                               // 5
    k_box_x_div<<<NCELLS / 4, 256>>>();                            // 6
    k_gather<<<(N_PTS * 32 + 255) / 256, 256>>>(coords, Wp, out);  // 7
}